// round 9
// baseline (speedup 1.0000x reference)
#include <cuda_runtime.h>

#define RES    128
#define FEAT   18
#define NBIN   4096                 // 16^3 macrocells of 8^3 cells
#define MAXPTS 2097152
#define TILE_F2 6561                // 9*9*9 cells * 9 float2 = 52488 B

__device__ int g_cnt[NBIN];
__device__ int g_base[NBIN + 1];
__device__ int g_cursor[NBIN];
__device__ int g_binid[MAXPTS];
__device__ int g_sidx[MAXPTS];

// ---- shared point setup: inverse-transform + cell/weight computation ----
__device__ __forceinline__ void pt_setup(const float* __restrict__ pts,
                                         const float* __restrict__ T,
                                         int n,
                                         int& ix0, int& iy0, int& iz0,
                                         float& wx1, float& wy1, float& wz1)
{
    const float a  = __ldg(T + 0), b  = __ldg(T + 1), c_ = __ldg(T + 2),  tx = __ldg(T + 3);
    const float d  = __ldg(T + 4), e  = __ldg(T + 5), f  = __ldg(T + 6),  ty = __ldg(T + 7);
    const float g  = __ldg(T + 8), h  = __ldg(T + 9), ii = __ldg(T + 10), tz = __ldg(T + 11);

    const float det = a * (e * ii - f * h) - b * (d * ii - f * g) + c_ * (d * h - e * g);
    const float rd  = 1.0f / det;
    const float m00 = (e * ii - f * h) * rd,  m01 = (c_ * h - b * ii) * rd,  m02 = (b * f - c_ * e) * rd;
    const float m10 = (f * g - d * ii) * rd,  m11 = (a * ii - c_ * g) * rd,  m12 = (c_ * d - a * f) * rd;
    const float m20 = (d * h - e * g) * rd,   m21 = (b * g - a * h) * rd,    m22 = (a * e - b * d) * rd;

    const float qx = __ldcs(pts + 3 * n + 0) - tx;
    const float qy = __ldcs(pts + 3 * n + 1) - ty;
    const float qz = __ldcs(pts + 3 * n + 2) - tz;

    const float px = (m00 * qx + m01 * qy + m02 * qz) * (float)(RES - 1);
    const float py = (m10 * qx + m11 * qy + m12 * qz) * (float)(RES - 1);
    const float pz = (m20 * qx + m21 * qy + m22 * qz) * (float)(RES - 1);

    const float fx = floorf(px), fy = floorf(py), fz = floorf(pz);
    wx1 = px - fx;  wy1 = py - fy;  wz1 = pz - fz;

    ix0 = max(0, min(RES - 1, (int)fx));
    iy0 = max(0, min(RES - 1, (int)fy));
    iz0 = max(0, min(RES - 1, (int)fz));
}

// ---- pass 0: zero bin counters ----
__global__ void k_zero() {
    int t = blockIdx.x * blockDim.x + threadIdx.x;
    if (t < NBIN) g_cnt[t] = 0;
}

// ---- pass 1: count points per macrocell, remember bin id ----
__global__ void k_count(const float* __restrict__ pts,
                        const float* __restrict__ T, int N) {
    int n = blockIdx.x * blockDim.x + threadIdx.x;
    if (n >= N) return;
    int ix0, iy0, iz0; float wx, wy, wz;
    pt_setup(pts, T, n, ix0, iy0, iz0, wx, wy, wz);
    const int bin = (ix0 >> 3) | ((iy0 >> 3) << 4) | ((iz0 >> 3) << 8);
    g_binid[n] = bin;
    atomicAdd(&g_cnt[bin], 1);
}

// ---- pass 2: exclusive scan over 4096 bins (single block) ----
__global__ void k_scan() {
    __shared__ int s[1024];
    const int t = threadIdx.x;
    int v[4], sum = 0;
    #pragma unroll
    for (int k = 0; k < 4; k++) { v[k] = g_cnt[t * 4 + k]; sum += v[k]; }
    s[t] = sum;
    __syncthreads();
    #pragma unroll
    for (int off = 1; off < 1024; off <<= 1) {
        int x = (t >= off) ? s[t - off] : 0;
        __syncthreads();
        s[t] += x;
        __syncthreads();
    }
    int run = s[t] - sum;   // exclusive
    #pragma unroll
    for (int k = 0; k < 4; k++) {
        g_base[t * 4 + k]   = run;
        g_cursor[t * 4 + k] = run;
        run += v[k];
    }
    if (t == 1023) g_base[NBIN] = run;
}

// ---- pass 3: scatter point indices into bin-sorted order ----
__global__ void k_scatter(int N) {
    int n = blockIdx.x * blockDim.x + threadIdx.x;
    if (n >= N) return;
    const int b    = g_binid[n];
    const int slot = atomicAdd(&g_cursor[b], 1);
    g_sidx[slot] = n;
}

// ---- pass 4: per-bin interpolation from a smem codebook tile ----
__global__ __launch_bounds__(256)
void k_interp(const float* __restrict__ pts,
              const float* __restrict__ cb,
              const float* __restrict__ T,
              float* __restrict__ out, int N)
{
    extern __shared__ float2 tile[];   // [9][9][9] cells x 9 float2 = 52488 B

    const int b  = blockIdx.x;
    const int mx = b & 15, my = (b >> 4) & 15, mz = b >> 8;

    // load (8+1)^3-cell tile, edge-clamped, coalesced float2
    for (int t = threadIdx.x; t < TILE_F2; t += blockDim.x) {
        const int seg = t / 81;          // lz*9 + ly
        const int c   = t % 81;          // lx*9 + fo
        const int lz = seg / 9, ly = seg % 9;
        const int lx = c / 9,  fo = c % 9;
        const int sx = min(8 * mx + lx, RES - 1);
        const int sy = min(8 * my + ly, RES - 1);
        const int sz = min(8 * mz + lz, RES - 1);
        tile[t] = __ldg((const float2*)cb +
                        (size_t)(sx + sy * RES + sz * RES * RES) * (FEAT / 2) + fo);
    }
    __syncthreads();

    const int s0 = g_base[b];
    const int e0 = g_base[b + 1];

    for (int i = s0 + threadIdx.x; i < e0; i += blockDim.x) {
        const int n = g_sidx[i];

        int ix0, iy0, iz0; float wx1, wy1, wz1;
        pt_setup(pts, T, n, ix0, iy0, iz0, wx1, wy1, wz1);

        const float wx0 = 1.0f - wx1, wy0 = 1.0f - wy1, wz0 = 1.0f - wz1;

        const int lx0 = ix0 - 8 * mx;
        const int ly0 = iy0 - 8 * my;
        const int lz0 = iz0 - 8 * mz;
        const int lx1 = min(ix0 + 1, RES - 1) - 8 * mx;
        const int ly1 = min(iy0 + 1, RES - 1) - 8 * my;
        const int lz1 = min(iz0 + 1, RES - 1) - 8 * mz;

        float2 acc[FEAT / 2];
        #pragma unroll
        for (int j = 0; j < FEAT / 2; j++) acc[j] = make_float2(0.0f, 0.0f);

        #pragma unroll
        for (int r = 0; r < 8; r++) {
            const int lx = (r & 1) ? lx1 : lx0;
            const int ly = (r & 2) ? ly1 : ly0;
            const int lz = (r & 4) ? lz1 : lz0;
            const float w = ((r & 1) ? wx1 : wx0) *
                            ((r & 2) ? wy1 : wy0) *
                            ((r & 4) ? wz1 : wz0);
            const float2* row = tile + (size_t)(lz * 81 + ly * 9 + lx) * (FEAT / 2);
            #pragma unroll
            for (int j = 0; j < FEAT / 2; j++) {
                const float2 v = row[j];
                acc[j].x = fmaf(w, v.x, acc[j].x);
                acc[j].y = fmaf(w, v.y, acc[j].y);
            }
        }

        float2* op = (float2*)(out + (size_t)n * FEAT);
        #pragma unroll
        for (int j = 0; j < FEAT / 2; j++)
            __stcs(op + j, acc[j]);
    }
}

extern "C" void kernel_launch(void* const* d_in, const int* in_sizes, int n_in,
                              void* d_out, int out_size)
{
    const float* pts = (const float*)d_in[0];
    const float* cb  = (const float*)d_in[1];
    const float* T   = (const float*)d_in[2];
    float* out       = (float*)d_out;

    const int N = in_sizes[0] / 3;
    const int pblocks = (N + 255) / 256;

    static bool attr_set = false;
    if (!attr_set) {
        cudaFuncSetAttribute(k_interp, cudaFuncAttributeMaxDynamicSharedMemorySize,
                             TILE_F2 * (int)sizeof(float2));
        attr_set = true;
    }

    k_zero<<<(NBIN + 255) / 256, 256>>>();
    k_count<<<pblocks, 256>>>(pts, T, N);
    k_scan<<<1, 1024>>>();
    k_scatter<<<pblocks, 256>>>(N);
    k_interp<<<NBIN, 256, TILE_F2 * sizeof(float2)>>>(pts, cb, T, out, N);
}

// round 10
// speedup vs baseline: 1.5882x; 1.5882x over previous
#include <cuda_runtime.h>

#define RES   128
#define FEAT  18
#define TPB   256
#define CBSIZE (RES * RES * RES * FEAT)   // 37748736 floats

// 256-bit gather load with L2 evict_last residency hint (codebook has reuse).
__device__ __forceinline__ void ldg256_el(const float* p, float* r) {
    unsigned a0, a1, a2, a3, a4, a5, a6, a7;
    asm volatile("ld.global.nc.L2::evict_last.v8.b32 {%0,%1,%2,%3,%4,%5,%6,%7}, [%8];"
                 : "=r"(a0), "=r"(a1), "=r"(a2), "=r"(a3),
                   "=r"(a4), "=r"(a5), "=r"(a6), "=r"(a7)
                 : "l"(p));
    r[0] = __uint_as_float(a0); r[1] = __uint_as_float(a1);
    r[2] = __uint_as_float(a2); r[3] = __uint_as_float(a3);
    r[4] = __uint_as_float(a4); r[5] = __uint_as_float(a5);
    r[6] = __uint_as_float(a6); r[7] = __uint_as_float(a7);
}

__global__ __launch_bounds__(TPB)
void densegrid_v8_kernel(const float* __restrict__ pts,
                         const float* __restrict__ cb,
                         const float* __restrict__ T,
                         float* __restrict__ out,
                         int N)
{
    __shared__ float stage[TPB * FEAT];   // 18 KB

    const int tid = threadIdx.x;
    const int n   = blockIdx.x * TPB + tid;

    if (n < N) {
        // ---- transform inverse (broadcast) ----
        const float a  = __ldg(T + 0), b  = __ldg(T + 1), c_ = __ldg(T + 2),  tx = __ldg(T + 3);
        const float d  = __ldg(T + 4), e  = __ldg(T + 5), f  = __ldg(T + 6),  ty = __ldg(T + 7);
        const float g  = __ldg(T + 8), h  = __ldg(T + 9), ii = __ldg(T + 10), tz = __ldg(T + 11);

        const float det = a * (e * ii - f * h) - b * (d * ii - f * g) + c_ * (d * h - e * g);
        const float rd  = 1.0f / det;
        const float m00 = (e * ii - f * h) * rd,  m01 = (c_ * h - b * ii) * rd,  m02 = (b * f - c_ * e) * rd;
        const float m10 = (f * g - d * ii) * rd,  m11 = (a * ii - c_ * g) * rd,  m12 = (c_ * d - a * f) * rd;
        const float m20 = (d * h - e * g) * rd,   m21 = (b * g - a * h) * rd,    m22 = (a * e - b * d) * rd;

        const float qx = __ldcs(pts + 3 * n + 0) - tx;
        const float qy = __ldcs(pts + 3 * n + 1) - ty;
        const float qz = __ldcs(pts + 3 * n + 2) - tz;

        float px = (m00 * qx + m01 * qy + m02 * qz) * (float)(RES - 1);
        float py = (m10 * qx + m11 * qy + m12 * qz) * (float)(RES - 1);
        float pz = (m20 * qx + m21 * qy + m22 * qz) * (float)(RES - 1);

        const float fx = floorf(px), fy = floorf(py), fz = floorf(pz);
        const float wx = px - fx,    wy = py - fy,    wz = pz - fz;

        int ix0 = max(0, min(RES - 1, (int)fx));
        int iy0 = max(0, min(RES - 1, (int)fy));
        int iz0 = max(0, min(RES - 1, (int)fz));
        const int ix1 = min(ix0 + 1, RES - 1);
        const int iy1 = min(iy0 + 1, RES - 1);
        const int iz1 = min(iz0 + 1, RES - 1);

        const float wx0 = 1.0f - wx, wy0 = 1.0f - wy, wz0 = 1.0f - wz;

        const float w[8] = {
            wx0 * wy0 * wz0,  wx  * wy0 * wz0,
            wx0 * wy  * wz0,  wx  * wy  * wz0,
            wx0 * wy0 * wz,   wx  * wy0 * wz,
            wx0 * wy  * wz,   wx  * wy  * wz
        };

        const int ry0 = iy0 * RES, ry1 = iy1 * RES;
        const int rz0 = iz0 * RES * RES, rz1 = iz1 * RES * RES;
        const int o[8] = {
            (ix0 + ry0 + rz0) * FEAT,  (ix1 + ry0 + rz0) * FEAT,
            (ix0 + ry1 + rz0) * FEAT,  (ix1 + ry1 + rz0) * FEAT,
            (ix0 + ry0 + rz1) * FEAT,  (ix1 + ry0 + rz1) * FEAT,
            (ix0 + ry1 + rz1) * FEAT,  (ix1 + ry1 + rz1) * FEAT
        };

        float acc[FEAT];
        #pragma unroll
        for (int j = 0; j < FEAT; j++) acc[j] = 0.0f;

        // ---- 8 corners: 3x LDG.256 from a 32B-aligned 96B window each ----
        #pragma unroll
        for (int c = 0; c < 8; c++) {
            const int   oc = o[c];
            const int   ba = oc & ~7;          // 32B-aligned float index (never needs end-clamp: max par=6, 24-float window fits)
            const int   par = oc - ba;         // 0, 2, 4, or 6
            const bool  b0 = (par & 2) != 0;
            const bool  b1 = (par & 4) != 0;
            const float wc = w[c];

            float win[24];
            ldg256_el(cb + ba +  0, win +  0);
            ldg256_el(cb + ba +  8, win +  8);
            ldg256_el(cb + ba + 16, win + 16);

            // acc[j] += wc * win[j + par]
            #pragma unroll
            for (int j = 0; j < FEAT; j++) {
                const float t = b0 ? win[j + 2] : win[j];
                const float u = b0 ? win[j + 6] : win[j + 4];
                const float v = b1 ? u : t;
                acc[j] = fmaf(wc, v, acc[j]);
            }
        }

        #pragma unroll
        for (int j = 0; j < FEAT; j++)
            stage[tid * FEAT + j] = acc[j];
    }

    __syncthreads();

    // ---- coalesced block output: 256*18 floats = 1152 float4, streaming ----
    const long long blockBase = (long long)blockIdx.x * TPB * FEAT;
    const long long remain    = (long long)N * FEAT - blockBase;

    if (remain >= (long long)TPB * FEAT) {
        const float4* s4 = (const float4*)stage;
        float4* o4 = (float4*)(out + blockBase);
        #pragma unroll
        for (int i = tid; i < TPB * FEAT / 4; i += TPB)
            __stcs(o4 + i, s4[i]);
    } else if (remain > 0) {
        float* op = out + blockBase;
        for (int i = tid; i < (int)remain; i += TPB)
            __stcs(op + i, stage[i]);
    }
}

extern "C" void kernel_launch(void* const* d_in, const int* in_sizes, int n_in,
                              void* d_out, int out_size)
{
    const float* pts = (const float*)d_in[0];
    const float* cb  = (const float*)d_in[1];
    const float* T   = (const float*)d_in[2];
    float* out       = (float*)d_out;

    const int N = in_sizes[0] / 3;
    const int blocks = (N + TPB - 1) / TPB;
    densegrid_v8_kernel<<<blocks, TPB>>>(pts, cb, T, out, N);
}